// round 17
// baseline (speedup 1.0000x reference)
#include <cuda_runtime.h>

// ============================================================================
// HamGNNInspiredNodeBlock: FullyConnectedTensorProduct(x,x) + o3.Linear skip
// irreps = 32x0e + 32x1o + 16x2e  (dims 32 + 96 + 80 = 208), 200000 nodes
// R16: A-read multiplicity 4->2 for groups 0/1 (uv-split 4 x ch-split 2),
//      1 CTA/SM (registers for crossbar bytes), pipelined chunks kept.
// ============================================================================

#define NNODES   200000
#define TOTDIM   208
#define TN       64          // nodes per CTA (lane holds nodes lane & lane+32 packed)
#define NTHREADS 256
#define NBLOCKS  (NNODES / TN)   // 3125
#define CU       16          // uv-chunk size (divides every UVC exactly)
#define TPWSIZE  208896
#define LNWSIZE  2304

// dynamic smem partition (float2 counts)
#define XS2_N (TOTDIM * 32)     // 6656 f2 = 53248 B : x staged [feat][lane]
#define AS2_N (2 * CU * 5 * 32) // 5120 f2 = 40960 B : A double buffer
#define WS2_N (2 * CU * 32)     // 1024 f2 =  8192 B : W double buffer (w,w)
#define AS_STRIDE (CU * 5 * 32) // 2560 f2 per buffer
#define WS_STRIDE (CU * 32)     //  512 f2 per buffer
#define SMEM_DYN ((XS2_N + AS2_N + WS2_N) * 8)   // 102400 B

// ---------------------------------------------------------------------------
// compile-time real-basis Wigner 3j (mirrors e3nn construction exactly)
// ---------------------------------------------------------------------------
struct W3J { int n; int ii[126]; int jj[126]; int kk[126]; float vv[126]; };
struct QM  { double re[5][5]; double im[5][5]; };

constexpr double cabsd(double x){ return x < 0 ? -x : x; }
constexpr double csqrt(double x){
  if (x <= 0.0) return 0.0;
  double g = x > 1.0 ? x : 1.0;
  for (int i = 0; i < 60; i++) g = 0.5*(g + x/g);
  return g;
}

constexpr double ccg(int j1,int m1,int j2,int m2,int j3,int m3){
  if (m1 + m2 != m3) return 0.0;
  double f[8] = {1,1,2,6,24,120,720,5040};
  double pref = csqrt((2.0*j3+1.0)*f[j3+j1-j2]*f[j3-j1+j2]*f[j1+j2-j3]/f[j1+j2+j3+1]);
  pref = pref * csqrt(f[j3+m3]*f[j3-m3]*f[j1-m1]*f[j1+m1]*f[j2-m2]*f[j2+m2]);
  int kmin = 0;
  if (j2-j3-m1 > kmin) kmin = j2-j3-m1;
  if (j1-j3+m2 > kmin) kmin = j1-j3+m2;
  int kmax = j1+j2-j3;
  if (j1-m1 < kmax) kmax = j1-m1;
  if (j2+m2 < kmax) kmax = j2+m2;
  double s = 0.0;
  for (int k = kmin; k <= kmax; k++){
    double d = f[k]*f[j1+j2-j3-k]*f[j1-m1-k]*f[j2+m2-k]*f[j3-j2+m1+k]*f[j3-j1-m2+k];
    s += ((k & 1) ? -1.0 : 1.0)/d;
  }
  return pref*s;
}

constexpr QM cq(int l){
  QM q{};
  double s = csqrt(0.5);
  for (int m = -l; m < 0; m++){ q.re[l+m][l-m] = s; q.im[l+m][l+m] = -s; }
  q.re[l][l] = 1.0;
  for (int m = 1; m <= l; m++){
    double sg = (m & 1) ? -1.0 : 1.0;
    q.re[l+m][l+m] = sg*s;
    q.im[l+m][l-m] = sg*s;
  }
  double pr = 1.0, pi = 0.0;               // (-i)^l
  if ((l & 3) == 1){ pr = 0.0; pi = -1.0; }
  else if ((l & 3) == 2){ pr = -1.0; pi = 0.0; }
  else if ((l & 3) == 3){ pr = 0.0; pi = 1.0; }
  QM o{};
  for (int a = 0; a < 5; a++)
    for (int b = 0; b < 5; b++){
      o.re[a][b] = q.re[a][b]*pr - q.im[a][b]*pi;
      o.im[a][b] = q.re[a][b]*pi + q.im[a][b]*pr;
    }
  return o;
}

constexpr W3J cw3j(int l1, int l2, int l3, int outk){
  QM q1 = cq(l1), q2 = cq(l2), q3 = cq(l3);
  int d1 = 2*l1+1, d2 = 2*l2+1, d3 = 2*l3+1;
  double W[5][5][5] = {};
  for (int i = 0; i < d1; i++)
    for (int j = 0; j < d2; j++)
      for (int k = 0; k < d3; k++){
        double val = 0.0;
        for (int a = 0; a < d1; a++)
          for (int b = 0; b < d2; b++){
            int m1 = a-l1, m2 = b-l2, m3 = m1+m2;
            if (m3 < -l3 || m3 > l3) continue;
            double C = ccg(l1,m1,l2,m2,l3,m3);
            if (C == 0.0) continue;
            int c = m3+l3;
            double tr = q1.re[a][i]*q2.re[b][j] - q1.im[a][i]*q2.im[b][j];
            double ti = q1.re[a][i]*q2.im[b][j] + q1.im[a][i]*q2.re[b][j];
            val += (tr*q3.re[c][k] + ti*q3.im[c][k]) * C;
          }
        W[i][j][k] = val;
      }
  double nrm = 0.0;
  for (int i = 0; i < d1; i++)
    for (int j = 0; j < d2; j++)
      for (int k = 0; k < d3; k++) nrm += W[i][j][k]*W[i][j][k];
  nrm = csqrt(nrm);
  // PATH_COEFF = sqrt((2*l3+1)/FAN); FAN = {2304, 3072, 2304}
  double pc0 = csqrt(1.0/2304.0), pc1 = csqrt(3.0/3072.0), pc2 = csqrt(5.0/2304.0);
  double cf = (outk == 0 ? pc0 : (outk == 1 ? pc1 : pc2)) / nrm;
  W3J t{};
  for (int i = 0; i < d1; i++)
    for (int j = 0; j < d2; j++)
      for (int k = 0; k < d3; k++){
        double v = W[i][j][k];
        if (cabsd(v) > 1e-9*nrm){
          t.ii[t.n] = i; t.jj[t.n] = j; t.kk[t.n] = k;
          t.vv[t.n] = (float)(v*cf); t.n++;
        }
      }
  return t;
}

constexpr W3J TABS[11] = {
  cw3j(0,0,0,0), cw3j(0,1,1,1), cw3j(0,2,2,2), cw3j(1,0,1,1), cw3j(1,1,0,0),
  cw3j(1,1,2,2), cw3j(1,2,1,1), cw3j(2,0,2,2), cw3j(2,1,1,1), cw3j(2,2,0,0),
  cw3j(2,2,2,2)
};

// ---------------------------------------------------------------------------
// packed f32x2 helpers
// ---------------------------------------------------------------------------
union F2U { float2 f; unsigned long long u; };

__device__ __forceinline__ float2 f2fma(float2 a, float2 b, float2 c){
  F2U A, B, C, D; A.f = a; B.f = b; C.f = c;
  asm("fma.rn.f32x2 %0, %1, %2, %3;" : "=l"(D.u) : "l"(A.u), "l"(B.u), "l"(C.u));
  return D.f;
}
__device__ __forceinline__ float2 f2mul(float2 a, float2 b){
  F2U A, B, D; A.f = a; B.f = b;
  asm("mul.rn.f32x2 %0, %1, %2;" : "=l"(D.u) : "l"(A.u), "l"(B.u));
  return D.f;
}

// statically-unrolled CG contraction for one (u,v): all table reads constexpr
template<int PID, int T, int NT>
__device__ __forceinline__ void agenAll(const float2* x1, const float2* x2, float2* a){
  if constexpr (T < NT){
    constexpr int   i = TABS[PID].ii[T];
    constexpr int   j = TABS[PID].jj[T];
    constexpr int   k = TABS[PID].kk[T];
    constexpr float v = TABS[PID].vv[T];
    a[k] = f2fma(f2mul(x1[i], x2[j]), make_float2(v, v), a[k]);
    agenAll<PID, T+1, NT>(x1, x2, a);
  }
}

// ---------------------------------------------------------------------------
// accumulate one chunk: c = ug, ug+CSTR, ...; channels [woBase, woBase+NCHW);
// k range [KB, KB+KN), acc channel stride ASTR.
// ---------------------------------------------------------------------------
template<int KN, int KB, int NCHW, int ASTR, int M3, int CSTR>
__device__ __forceinline__
void accumChunk(const float2* __restrict__ As, const float2* __restrict__ Ws,
                int ug, int woBase, int lane, float2* __restrict__ acc)
{
  #pragma unroll 2
  for (int c = ug; c < CU; c += CSTR){
    float2 av[KN];
    #pragma unroll
    for (int k = 0; k < KN; k++) av[k] = As[(c*5 + KB + k)*32 + lane];
    const float4* w4 = (const float4*)(Ws + c*M3 + woBase);
    #pragma unroll
    for (int cp = 0; cp < NCHW/2; cp++){
      float4 wq = w4[cp];
      float2 wa = make_float2(wq.x, wq.y);
      float2 wb = make_float2(wq.z, wq.w);
      #pragma unroll
      for (int k = 0; k < KN; k++){
        acc[(2*cp  )*ASTR + k] = f2fma(av[k], wa, acc[(2*cp  )*ASTR + k]);
        acc[(2*cp+1)*ASTR + k] = f2fma(av[k], wb, acc[(2*cp+1)*ASTR + k]);
      }
    }
  }
}

// ---------------------------------------------------------------------------
// one path, software-pipelined over chunks (double-buffered A and W)
//   gen:        warp handles c = 2*warp, 2*warp+1 (u is chunk-constant)
//   accumulate: KSPL=1: warps = uv2 x ch2 x k{0-2|3-4}      (group 2, M3=16)
//               USPL=4: warps = uv4 x ch2                    (groups 0/1, M3=32)
// ---------------------------------------------------------------------------
template<int PID,int UVC,int M2SH,int D1,int D2,int OFF1,int OFF2,int KD,int M3,
         int LIN,int KSPL,int USPL>
__device__ __forceinline__
void doPath(const float2* __restrict__ xs2, float2* __restrict__ AsB,
            float2* __restrict__ WsB, const float* __restrict__ wsrc,
            float linScale, int warp, int lane, int tid,
            float2* __restrict__ acc)
{
  const int M2  = 1 << M2SH;
  const int nCh = UVC / CU;
  const int kh  = warp & 1;

  int ug, woBase;
  if constexpr (KSPL)          { ug = warp >> 2; woBase = ((warp >> 1) & 1) * (M3/2); }
  else if constexpr (USPL == 4){ ug = warp >> 1; woBase = (warp & 1) * (M3/2); }
  else                         { ug = warp >> 2; woBase = (warp & 3) * (M3/4); }

  auto gen = [&](int t, float2* As, float2* Ws){
    int uv0 = t * CU;
    // W stage (duplicated (w,w)); CU*M3 is 256 or 512
    {
      const float* wp = wsrc + uv0*M3;
      #pragma unroll
      for (int r = 0; r < (CU*M3 + NTHREADS - 1)/NTHREADS; r++){
        int idx = tid + r*NTHREADS;
        if ((CU*M3 % NTHREADS == 0) || idx < CU*M3){
          float w = wp[idx];
          Ws[idx] = make_float2(w, w);
        }
      }
    }
    if constexpr (LIN){
      #pragma unroll
      for (int s = 0; s < 2; s++){
        int c = 2*warp + s;
        int uv = uv0 + c;
        #pragma unroll
        for (int k = 0; k < KD; k++){
          float2 v = xs2[(OFF1 + uv*D1 + k)*32 + lane];
          As[(c*5 + k)*32 + lane] = make_float2(v.x*linScale, v.y*linScale);
        }
      }
    } else {
      // u constant across the whole chunk (CU=16 divides M2)
      int u  = uv0 >> M2SH;
      int v0 = uv0 & (M2 - 1);
      float2 x1[D1];
      const float2* p1 = xs2 + (OFF1 + u*D1)*32 + lane;
      #pragma unroll
      for (int i = 0; i < D1; i++) x1[i] = p1[i*32];
      #pragma unroll
      for (int s = 0; s < 2; s++){
        int c = 2*warp + s;
        int v = v0 + c;
        float2 x2[D2];
        const float2* p2 = xs2 + (OFF2 + v*D2)*32 + lane;
        #pragma unroll
        for (int j = 0; j < D2; j++) x2[j] = p2[j*32];
        float2 a[KD];
        #pragma unroll
        for (int k = 0; k < KD; k++) a[k] = make_float2(0.f, 0.f);
        agenAll<PID, 0, TABS[PID].n>(x1, x2, a);
        #pragma unroll
        for (int k = 0; k < KD; k++) As[(c*5 + k)*32 + lane] = a[k];
      }
    }
  };

  auto accum = [&](int b){
    const float2* As = AsB + b*AS_STRIDE;
    const float2* Ws = WsB + b*WS_STRIDE;
    if constexpr (KSPL){
      // KD==5: k 0-2 on kh=0 warps, k 3-4 on kh=1 warps; acc stride 3
      if (kh) accumChunk<2, 3, M3/2, 3, M3, 2>(As, Ws, ug, woBase, lane, acc);
      else    accumChunk<3, 0, M3/2, 3, M3, 2>(As, Ws, ug, woBase, lane, acc);
    } else if constexpr (USPL == 4){
      accumChunk<KD, 0, M3/2, KD, M3, 4>(As, Ws, ug, woBase, lane, acc);
    } else {
      accumChunk<KD, 0, M3/4, KD, M3, 2>(As, Ws, ug, woBase, lane, acc);
    }
  };

  gen(0, AsB, WsB);
  __syncthreads();
  for (int t = 1; t < nCh; t++){
    int b = t & 1;
    gen(t, AsB + b*AS_STRIDE, WsB + b*WS_STRIDE);
    accum((t-1) & 1);
    __syncthreads();
  }
  accum((nCh-1) & 1);
  __syncthreads();
}

// ---------------------------------------------------------------------------
// group flush: nUG-phase uv-group reduce into padded smem rows, coalesced STG
// f = (woBase+ch)*kdtot + kb + k  (disjoint across warps within a phase)
// ---------------------------------------------------------------------------
template<int GF, int GOFF>
__device__ __forceinline__
void flushGroup(const float2* __restrict__ acc, float* __restrict__ fbuf,
                float* __restrict__ outp, int node0, int lane, int tid,
                int ug, int nUG, int woBase, int nchw, int kdtot, int kb,
                int kn, int astr)
{
  const int FP = GF + 1;                 // odd pad -> conflict-free rows
  for (int p = 0; p < nUG; p++){
    if (ug == p){
      for (int ch = 0; ch < nchw; ch++)
        for (int k = 0; k < kn; k++){
          int f = (woBase + ch)*kdtot + kb + k;
          float2 v = acc[ch*astr + k];
          if (p == 0){
            fbuf[ lane      *FP + f] = v.x;
            fbuf[(lane + 32)*FP + f] = v.y;
          } else {
            fbuf[ lane      *FP + f] += v.x;
            fbuf[(lane + 32)*FP + f] += v.y;
          }
        }
    }
    __syncthreads();
  }
  for (int idx = tid; idx < 64*GF; idx += NTHREADS){
    int f = idx % GF, n = idx / GF;
    outp[(node0 + n)*TOTDIM + GOFF + f] = fbuf[n*FP + f];
  }
  __syncthreads();   // fbuf (As region) reused by next group
}

// ---------------------------------------------------------------------------
__global__ void __launch_bounds__(NTHREADS, 1)
mainK(const float* __restrict__ x, const float* __restrict__ tpw,
      const float* __restrict__ lnw, float* __restrict__ out)
{
  extern __shared__ char smRaw[];
  float2* xs2 = (float2*)smRaw;            // [feat][lane] packed node pairs
  float2* AsB = xs2 + XS2_N;               // A double buffer
  float2* WsB = AsB + AS2_N;               // W double buffer
  float*  fbuf = (float*)AsB;              // group flush buffer (reuses As)

  int tid  = threadIdx.x;
  int lane = tid & 31;
  int warp = tid >> 5;
  int node0 = blockIdx.x * TN;

  // stage x packed: lane-fast node mapping -> conflict-free STS
  float* xf = (float*)xs2;
  for (int idx = tid; idx < TN*TOTDIM; idx += NTHREADS){
    int n = idx & 63, f = idx >> 6;
    xf[(f*32 + (n & 31))*2 + (n >> 5)] = x[(node0 + n)*TOTDIM + f];
  }
  __syncthreads();

  const float LS01 = 0.17677669529663689f;  // 1/sqrt(32)
  const float LS2  = 0.25f;                 // 1/sqrt(16)

  // ================= group 0 : output irrep 0 (32x0e, dims [0,32)) ==========
  // accumulate split: uv4 x ch2 (A-read multiplicity 2)
  {
    float2 acc[16];
    #pragma unroll
    for (int i = 0; i < 16; i++) acc[i] = make_float2(0.f, 0.f);
    //     PID  UVC M2SH D1 D2 OFF1 OFF2 KD M3 LIN KSPL USPL
    doPath<0, 1024, 5, 1, 1,   0,   0, 1, 32, 0, 0, 4>(xs2, AsB, WsB, tpw+0,      0.f, warp, lane, tid, acc);
    doPath<4, 1024, 5, 3, 3,  32,  32, 1, 32, 0, 0, 4>(xs2, AsB, WsB, tpw+106496, 0.f, warp, lane, tid, acc);
    doPath<9,  256, 4, 5, 5, 128, 128, 1, 32, 0, 0, 4>(xs2, AsB, WsB, tpw+196608, 0.f, warp, lane, tid, acc);
    doPath<0,   32, 0, 1, 1,   0,   0, 1, 32, 1, 0, 4>(xs2, AsB, WsB, lnw+0,     LS01, warp, lane, tid, acc);
    flushGroup<32, 0>(acc, fbuf, out, node0, lane, tid,
                      warp >> 1, 4, (warp & 1)*16, 16, 1, 0, 1, 1);
  }

  // ================= group 1 : output irrep 1 (32x1o, dims [32,128)) ========
  // accumulate split: uv4 x ch2 (A-read multiplicity 2); acc = 16ch x 3k
  {
    float2 acc[48];
    #pragma unroll
    for (int i = 0; i < 48; i++) acc[i] = make_float2(0.f, 0.f);
    doPath<1, 1024, 5, 1, 3,   0,  32, 3, 32, 0, 0, 4>(xs2, AsB, WsB, tpw+32768,  0.f, warp, lane, tid, acc);
    doPath<3, 1024, 5, 3, 1,  32,   0, 3, 32, 0, 0, 4>(xs2, AsB, WsB, tpw+73728,  0.f, warp, lane, tid, acc);
    doPath<6,  512, 4, 3, 5,  32, 128, 3, 32, 0, 0, 4>(xs2, AsB, WsB, tpw+155648, 0.f, warp, lane, tid, acc);
    doPath<8,  512, 5, 5, 3, 128,  32, 3, 32, 0, 0, 4>(xs2, AsB, WsB, tpw+180224, 0.f, warp, lane, tid, acc);
    doPath<0,   32, 0, 3, 1,  32,   0, 3, 32, 1, 0, 4>(xs2, AsB, WsB, lnw+1024,  LS01, warp, lane, tid, acc);
    flushGroup<96, 32>(acc, fbuf, out, node0, lane, tid,
                       warp >> 1, 4, (warp & 1)*16, 16, 3, 0, 3, 3);
  }

  // ================= group 2 : output irrep 2 (16x2e, dims [128,208)) =======
  // k-split accumulate: warps = uv2 x ch2 x k{0-2 | 3-4} (multiplicity 2)
  {
    float2 acc[24];
    #pragma unroll
    for (int i = 0; i < 24; i++) acc[i] = make_float2(0.f, 0.f);
    doPath< 2,  512, 4, 1, 5,   0, 128, 5, 16, 0, 1, 2>(xs2, AsB, WsB, tpw+65536,  0.f, warp, lane, tid, acc);
    doPath< 5, 1024, 5, 3, 3,  32,  32, 5, 16, 0, 1, 2>(xs2, AsB, WsB, tpw+139264, 0.f, warp, lane, tid, acc);
    doPath< 7,  512, 5, 5, 1, 128,   0, 5, 16, 0, 1, 2>(xs2, AsB, WsB, tpw+172032, 0.f, warp, lane, tid, acc);
    doPath<10,  256, 4, 5, 5, 128, 128, 5, 16, 0, 1, 2>(xs2, AsB, WsB, tpw+204800, 0.f, warp, lane, tid, acc);
    doPath< 0,   16, 0, 5, 1, 128,   0, 5, 16, 1, 1, 2>(xs2, AsB, WsB, lnw+2048,   LS2, warp, lane, tid, acc);
    int kh = warp & 1;
    flushGroup<80, 128>(acc, fbuf, out, node0, lane, tid,
                        warp >> 2, 2, ((warp>>1)&1)*8, 8, 5,
                        kh ? 3 : 0, kh ? 2 : 3, 3);
  }
}

// ---------------------------------------------------------------------------
extern "C" void kernel_launch(void* const* d_in, const int* in_sizes, int n_in,
                              void* d_out, int out_size)
{
  const float* x   = (const float*)d_in[0];
  const float* tpw = (n_in > 1) ? (const float*)d_in[1] : nullptr;
  const float* lnw = (n_in > 2) ? (const float*)d_in[2] : nullptr;
  for (int i = 0; i < n_in; i++){
    if      (in_sizes[i] == NNODES*TOTDIM) x   = (const float*)d_in[i];
    else if (in_sizes[i] == TPWSIZE)       tpw = (const float*)d_in[i];
    else if (in_sizes[i] == LNWSIZE)       lnw = (const float*)d_in[i];
  }

  (void)cudaFuncSetAttribute(mainK, cudaFuncAttributeMaxDynamicSharedMemorySize, SMEM_DYN);
  mainK<<<NBLOCKS, NTHREADS, SMEM_DYN>>>(x, tpw, lnw, (float*)d_out);
}